// round 13
// baseline (speedup 1.0000x reference)
#include <cuda_runtime.h>
#include <cuda_fp16.h>
#include <math.h>

#define B_   64
#define S_   4096
#define DEC_ 512
#define ENC_ 256
#define MT   64                                        // rows per k_scores tile

// ---------------- device scratch (allocation-free rule) ----------------
__device__ float2 g_dw[B_ * ENC_];                    // (dpe, Wa) per (b,f)
__device__ float  g_scores[B_ * S_];                  // compacted e = exp(score)
__device__ int    g_idx[B_ * S_];                     // unmasked index lists
__device__ int    g_cnt[B_];                          // unmasked counts
__device__ int    g_done[B_];                         // tile-completion counters
__device__ float  g_cpart[(size_t)B_ * 64 * ENC_];    // per-tile ctx partials
__device__ float  g_esum[B_ * 64];                    // per-tile sum of e
// We^T fp16 per K-chunk, LDSM-native block layout:
//   addr(n,kc) = (g*2+ks)*512 + h16*256 + (n&15)*16 + (kc&7)*2
__device__ __align__(16) unsigned char g_Bt[8][16384];

// ---------------- smem layout (bytes), per CTA = 43536 ----------------
#define OBI(buf)     ((unsigned)(buf) * 16384u)        // B fp16, 32K dbuf (buf0 reused: red)
#define OAI(buf)     (32768u + (unsigned)(buf) * 4096u) // A fp16 img (reused: sr)
#define ODW          40960u                            // float2[256]
#define OSIDX        43008u                            // int[64] row indices
#define OSE          43264u                            // float[64] e values (reused: esums)
#define OFLAG        43520u                            // int flag + float inv
#define SMEM_BYTES   43536u

static __device__ __forceinline__ unsigned s2u(const void* p) {
    unsigned a;
    asm("{ .reg .u64 t; cvta.to.shared.u64 t, %1; cvt.u32.u64 %0, t; }" : "=r"(a) : "l"(p));
    return a;
}
static __device__ __forceinline__ void cp16(unsigned dst, const void* src) {
    asm volatile("cp.async.cg.shared.global [%0], [%1], 16;" :: "r"(dst), "l"(src));
}
#define CP_COMMIT() asm volatile("cp.async.commit_group;" ::: "memory")
#define CP_WAIT0()  asm volatile("cp.async.wait_group 0;" ::: "memory")

#define LDM4(r, addr) \
    asm volatile("ldmatrix.sync.aligned.m8n8.x4.shared.b16 {%0,%1,%2,%3}, [%4];" \
        : "=r"((r)[0]), "=r"((r)[1]), "=r"((r)[2]), "=r"((r)[3]) : "r"(addr))

#define MMAH(d, a, b0, b1) \
    asm volatile("mma.sync.aligned.m16n8k16.row.col.f32.f16.f16.f32 " \
        "{%0,%1,%2,%3}, {%4,%5,%6,%7}, {%8,%9}, {%0,%1,%2,%3};" \
        : "+f"((d)[0]), "+f"((d)[1]), "+f"((d)[2]), "+f"((d)[3]) \
        : "r"((a)[0]), "r"((a)[1]), "r"((a)[2]), "r"((a)[3]), "r"(b0), "r"(b1))

static __device__ __forceinline__ float tanha(float x) {
    float y;
    asm("tanh.approx.f32 %0, %1;" : "=f"(y) : "f"(x));
    return y;
}

// ---------------------------------------------------------------------------
// k_pre: 3 roles. blocks 0-63: compact+zero attn+reset done; 64-127: We prep;
//        128-191: decproj (4-way ILP)
// ---------------------------------------------------------------------------
__global__ __launch_bounds__(1024)
void k_pre(const int* __restrict__ mask, float* __restrict__ attn,
           const float* __restrict__ We,
           const float* __restrict__ dh, const float* __restrict__ Wd,
           const float* __restrict__ bd, const float* __restrict__ be,
           const float* __restrict__ Wa) {
    const int bid = blockIdx.x, t = threadIdx.x;
    if (bid < 64) {                                   // ---- compact ----
        const int b = bid;
        if (t == 0) g_done[b] = 0;                    // reset finish counter
        const int4 m = ((const int4*)(mask + b * S_))[t];
        int c0 = m.x != 0, c1 = m.y != 0, c2 = m.z != 0, c3 = m.w != 0;
        const int ls = c0 + c1 + c2 + c3;
        const int lane = t & 31, wid = t >> 5;
        int ws = ls;
#pragma unroll
        for (int o = 1; o < 32; o <<= 1) {
            int v = __shfl_up_sync(~0u, ws, o);
            if (lane >= o) ws += v;
        }
        __shared__ int wsum[32];
        if (lane == 31) wsum[wid] = ws;
        __syncthreads();
        if (t < 32) {
            int v = wsum[t];
#pragma unroll
            for (int o = 1; o < 32; o <<= 1) {
                int u = __shfl_up_sync(~0u, v, o);
                if (t >= o) v += u;
            }
            wsum[t] = v;
        }
        __syncthreads();
        int p = (wid ? wsum[wid - 1] : 0) + (ws - ls);
        const int s = t * 4;
        int* gi = g_idx + b * S_;
        float* at = attn + b * S_;
        if (c0) gi[p++] = s;     else at[s]     = 0.f;
        if (c1) gi[p++] = s + 1; else at[s + 1] = 0.f;
        if (c2) gi[p++] = s + 2; else at[s + 2] = 0.f;
        if (c3) gi[p++] = s + 3; else at[s + 3] = 0.f;
        if (t == 1023) g_cnt[b] = p;
    } else if (bid < 128) {                           // ---- We prep ----
        const int k = (bid - 64) * 4 + (t >> 8), n = t & 255;
        float v = We[k * 256 + n];
        int ch = k >> 5, kc = k & 31;
        int g = n >> 4, ks = kc >> 4, h16 = (kc >> 3) & 1;
        unsigned addr = (unsigned)((g * 2 + ks) * 512 + h16 * 256 + (n & 15) * 16 +
                                   (kc & 7) * 2);
        *(__half*)&g_Bt[ch][addr] = __float2half_rn(v);
    } else {                                          // ---- decproj ----
        const int b = bid - 128;
        __shared__ float sdh[DEC_];
        __shared__ float part[4][256];
        if (t < DEC_) sdh[t] = dh[b * DEC_ + t];
        __syncthreads();
        const int f = t & 255, q = t >> 8;            // 4 slices of 128 d
        const float* wp = Wd + (q * 128) * 256 + f;
        const float* hp = sdh + q * 128;
        float a0 = 0.f, a1 = 0.f, a2 = 0.f, a3 = 0.f;
#pragma unroll 8
        for (int d = 0; d < 128; d += 4) {            // 4 independent chains
            a0 += hp[d]     * wp[(d)     * 256];
            a1 += hp[d + 1] * wp[(d + 1) * 256];
            a2 += hp[d + 2] * wp[(d + 2) * 256];
            a3 += hp[d + 3] * wp[(d + 3) * 256];
        }
        part[q][f] = (a0 + a1) + (a2 + a3);
        __syncthreads();
        if (t < 256) {
            float v = part[0][t] + part[1][t] + part[2][t] + part[3][t] + bd[t] + be[t];
            g_dw[b * 256 + t] = make_float2(v, Wa[t]);
        }
    }
}

// ---------------------------------------------------------------------------
// k_scores: 64-row compacted tile, fp16 HMMA + fused tanh/exp/context epilogue
//           + last-CTA-per-batch finish (ctx, attn)
// ---------------------------------------------------------------------------
static __device__ __forceinline__ void loadB(unsigned sb, int c, int tid) {
#pragma unroll
    for (int i = 0; i < 4; ++i) {
        int slot = tid + i * 256;
        cp16(sb + OBI(c & 1) + (unsigned)slot * 16u, &g_Bt[c][slot * 16]);
    }
    CP_COMMIT();
}
static __device__ __forceinline__ void cvtstore(unsigned dst, float4 v0, float4 v1) {
    float vf[8] = {v0.x, v0.y, v0.z, v0.w, v1.x, v1.y, v1.z, v1.w};
    unsigned hu[4];
#pragma unroll
    for (int q = 0; q < 4; ++q) {
        __half2 hp = __halves2half2(__float2half_rn(vf[2 * q]),
                                    __float2half_rn(vf[2 * q + 1]));
        hu[q] = *(unsigned*)&hp;
    }
    asm volatile("st.shared.v4.b32 [%0], {%1,%2,%3,%4};"
                 :: "r"(dst), "r"(hu[0]), "r"(hu[1]), "r"(hu[2]), "r"(hu[3]));
}

__global__ __launch_bounds__(256, 2)
void k_scores(const float* __restrict__ enc, float* __restrict__ ctx,
              float* __restrict__ attn) {
    const int b = blockIdx.x >> 6, tt = blockIdx.x & 63;
    const int cnt = g_cnt[b];
    const int tid = threadIdx.x;
    extern __shared__ __align__(16) unsigned char sm[];
    const unsigned sb = s2u(sm);

    if (tt * MT >= cnt) {                             // inactive: zero partials
        if (tid < 64) {
            float4 z = make_float4(0.f, 0.f, 0.f, 0.f);
            ((float4*)g_cpart)[((size_t)b * 64 + tt) * 64 + tid] = z;
        }
        if (tid == 0) g_esum[b * 64 + tt] = 0.f;
    } else {
        const int lane = tid & 31, w = tid >> 5;
        const int wr = w & 1, wc = w >> 1;

        const int r_ = tid >> 2, s_ = tid & 3;
        const int j = tt * MT + r_;
        const int row = g_idx[b * S_ + min(j, cnt - 1)];
        const float4* ap = (const float4*)(enc + ((size_t)b * S_ + row) * 256 + s_ * 8);
        const unsigned adst = (unsigned)(((r_ >> 4) * 2 + (s_ >> 1)) * 512 +
                                         (s_ & 1) * 256 + (r_ & 15) * 16);
        if ((tid & 3) == 0) ((int*)(sm + OSIDX))[r_] = row;

        loadB(sb, 0, tid);
        ((float2*)(sm + ODW))[tid] = g_dw[b * 256 + tid];

        float4 r0 = ap[0], r1 = ap[1];
        cvtstore(sb + OAI(0) + adst, r0, r1);
        CP_WAIT0();

        float acc[2][8][4];
#pragma unroll
        for (int mi = 0; mi < 2; ++mi)
#pragma unroll
            for (int ni = 0; ni < 8; ++ni)
#pragma unroll
                for (int q = 0; q < 4; ++q) acc[mi][ni][q] = 0.f;

        const unsigned a_lo = (unsigned)((lane & 15) * 16 + (lane >> 4) * 256);
        const unsigned b_lo = (unsigned)((lane & 7) * 16 + ((lane >> 4) & 1) * 128 +
                                         ((lane >> 3) & 1) * 256);

#pragma unroll 1
        for (int c = 0; c < 8; ++c) {
            const int buf = c & 1;
            __syncthreads();
            if (c < 7) {
                loadB(sb, c + 1, tid);
                r0 = ap[(c + 1) * 8];
                r1 = ap[(c + 1) * 8 + 1];
            }
            const unsigned ah_b = sb + OAI(buf) + a_lo;
            const unsigned bh_b = sb + OBI(buf) + b_lo;
#pragma unroll
            for (int ks = 0; ks < 2; ++ks) {
                unsigned af[2][4], bh[8][2];
#pragma unroll
                for (int mi = 0; mi < 2; ++mi)
                    LDM4(af[mi], ah_b + (unsigned)(((wr * 2 + mi) * 2 + ks) * 512));
#pragma unroll
                for (int p = 0; p < 4; ++p) {
                    const unsigned blk = (unsigned)(((wc * 4 + p) * 2 + ks) * 512);
                    unsigned r4[4];
                    LDM4(r4, bh_b + blk);
                    bh[2 * p][0] = r4[0]; bh[2 * p][1] = r4[1];
                    bh[2 * p + 1][0] = r4[2]; bh[2 * p + 1][1] = r4[3];
                }
#pragma unroll
                for (int mi = 0; mi < 2; ++mi)
#pragma unroll
                    for (int ni = 0; ni < 8; ++ni)
                        MMAH(acc[mi][ni], af[mi], bh[ni][0], bh[ni][1]);
            }
            if (c < 7) {
                cvtstore(sb + OAI(buf ^ 1) + adst, r0, r1);
                CP_WAIT0();
            }
        }

        // ---- Epilogue 1: score partials = sum_cols Wa * tanh(dpe + v) ----
        const float2* sdw = (const float2*)(sm + ODW);
        float* red = (float*)(sm + OBI(0));
#pragma unroll
        for (int mi = 0; mi < 2; ++mi) {
            float p0 = 0.f, p1 = 0.f;
#pragma unroll
            for (int ni = 0; ni < 8; ++ni) {
                int cc = wc * 64 + ni * 8 + 2 * (lane & 3);
                float2 w0 = sdw[cc], w1 = sdw[cc + 1];
                p0 += w0.y * tanha(acc[mi][ni][0] + w0.x) +
                      w1.y * tanha(acc[mi][ni][1] + w1.x);
                p1 += w0.y * tanha(acc[mi][ni][2] + w0.x) +
                      w1.y * tanha(acc[mi][ni][3] + w1.x);
            }
            p0 += __shfl_xor_sync(~0u, p0, 1); p0 += __shfl_xor_sync(~0u, p0, 2);
            p1 += __shfl_xor_sync(~0u, p1, 1); p1 += __shfl_xor_sync(~0u, p1, 2);
            if ((lane & 3) == 0) {
                int r = wr * 32 + mi * 16 + (lane >> 2);
                red[r * 5 + wc] = p0;
                red[(r + 8) * 5 + wc] = p1;
            }
        }
        __syncthreads();
        // ---- Epilogue 2: e = exp(score) (safe: |score| <= ~13) ----
        float* se = (float*)(sm + OSE);
        if (tid < MT) {
            float s = red[tid * 5] + red[tid * 5 + 1] + red[tid * 5 + 2] + red[tid * 5 + 3];
            float e = (tt * MT + tid < cnt) ? __expf(s) : 0.f;
            se[tid] = e;
            g_scores[b * S_ + tt * MT + tid] = e;
        }
        __syncthreads();
        if (tid < 32) {                               // tile sum of e
            float v = se[tid] + se[tid + 32];
#pragma unroll
            for (int o = 16; o; o >>= 1) v += __shfl_xor_sync(~0u, v, o);
            if (tid == 0) g_esum[b * 64 + tt] = v;
        }
        // ---- Epilogue 3: ctx partial = sum_r e[r] * enc[row_r,:] (L2 hits) ----
        {
            const int c4 = tid & 63, rg = tid >> 6;
            const int* sidx = (const int*)(sm + OSIDX);
            const float4* e4 = (const float4*)enc + (size_t)b * S_ * 64;
            float4 a4 = make_float4(0.f, 0.f, 0.f, 0.f);
#pragma unroll 4
            for (int i = 0; i < 16; ++i) {
                int r = rg * 16 + i;
                float wv = se[r];
                float4 ev = e4[(size_t)sidx[r] * 64 + c4];
                a4.x += wv * ev.x; a4.y += wv * ev.y; a4.z += wv * ev.z; a4.w += wv * ev.w;
            }
            float4* sr = (float4*)(sm + OAI(0));
            sr[rg * 64 + c4] = a4;
            __syncthreads();
            if (tid < 64) {
                float4 q0 = sr[tid], q1 = sr[64 + tid], q2 = sr[128 + tid],
                       q3 = sr[192 + tid];
                float4 o;
                o.x = q0.x + q1.x + q2.x + q3.x;
                o.y = q0.y + q1.y + q2.y + q3.y;
                o.z = q0.z + q1.z + q2.z + q3.z;
                o.w = q0.w + q1.w + q2.w + q3.w;
                ((float4*)g_cpart)[((size_t)b * 64 + tt) * 64 + tid] = o;
            }
        }
    }

    // ---- Finish: last CTA of batch b reduces tiles, writes ctx + attn ----
    __threadfence();                                  // publish this CTA's writes
    __syncthreads();
    int* flag = (int*)(sm + OFLAG);
    if (tid == 0) flag[0] = (atomicAdd(&g_done[b], 1) == 63);
    __syncthreads();
    if (!flag[0]) return;
    __threadfence();                                  // acquire all tiles' writes

    float* se = (float*)(sm + OSE);
    if (tid < 64) se[tid] = g_esum[b * 64 + tid];
    __syncthreads();
    if (tid < 32) {
        float v = se[tid] + se[tid + 32];
#pragma unroll
        for (int o = 16; o; o >>= 1) v += __shfl_xor_sync(~0u, v, o);
        if (tid == 0) ((float*)flag)[1] = 1.f / v;
    }
    __syncthreads();
    const float inv = ((float*)flag)[1];
    {                                                 // ctx = (sum tiles) * inv
        const float* cp = g_cpart + (size_t)b * 64 * 256 + tid;
        float a0 = 0.f, a1 = 0.f, a2 = 0.f, a3 = 0.f;
#pragma unroll 4
        for (int t2 = 0; t2 < 64; t2 += 4) {
            a0 += cp[(t2)     * 256];
            a1 += cp[(t2 + 1) * 256];
            a2 += cp[(t2 + 2) * 256];
            a3 += cp[(t2 + 3) * 256];
        }
        ctx[b * 256 + tid] = ((a0 + a1) + (a2 + a3)) * inv;
    }
    for (int j2 = tid; j2 < cnt; j2 += 256)           // attn scatter
        attn[b * S_ + g_idx[b * S_ + j2]] = g_scores[b * S_ + j2] * inv;
}

// ---------------------------------------------------------------------------
extern "C" void kernel_launch(void* const* d_in, const int* in_sizes, int n_in,
                              void* d_out, int out_size) {
    const float* dh   = (const float*)d_in[0];
    const float* enc  = (const float*)d_in[1];
    const int*   mask = (const int*)  d_in[2];
    const float* Wd   = (const float*)d_in[3];
    const float* bd   = (const float*)d_in[4];
    const float* We   = (const float*)d_in[5];
    const float* be   = (const float*)d_in[6];
    const float* Wa   = (const float*)d_in[7];
    // d_in[8] = ba: uniform shift on scores, cancels in softmax

    float* out  = (float*)d_out;
    float* ctx  = out;
    float* attn = out + B_ * ENC_;

    cudaFuncSetAttribute(k_scores, cudaFuncAttributeMaxDynamicSharedMemorySize, SMEM_BYTES);

    k_pre<<<192, 1024>>>(mask, attn, We, dh, Wd, bd, be, Wa);
    k_scores<<<B_ * 64, 256, SMEM_BYTES>>>(enc, ctx, attn);
}

// round 14
// speedup vs baseline: 1.1668x; 1.1668x over previous
#include <cuda_runtime.h>
#include <cuda_fp16.h>
#include <math.h>

#define B_   64
#define S_   4096
#define DEC_ 512
#define ENC_ 256
#define MT   64                                        // rows per k_scores tile

// ---------------- device scratch (allocation-free rule) ----------------
__device__ float2 g_dw[B_ * ENC_];                    // (dpe, Wa) per (b,f)
__device__ float  g_scores[B_ * S_];                  // compacted e = exp(score)
__device__ int    g_idx[B_ * S_];                     // unmasked index lists
__device__ int    g_cnt[B_];                          // unmasked counts
__device__ float  g_cpart[(size_t)B_ * 64 * ENC_];    // per-tile ctx partials
__device__ float  g_esum[B_ * 64];                    // per-tile sum of e
// We^T fp16 per K-chunk, LDSM-native block layout:
//   addr(n,kc) = (g*2+ks)*512 + h16*256 + (n&15)*16 + (kc&7)*2
__device__ __align__(16) unsigned char g_Bt[8][16384];

// ---------------- smem layout (bytes), per CTA = 43520 ----------------
#define OBI(buf)     ((unsigned)(buf) * 16384u)        // B fp16, 32K dbuf (buf0 reused: red)
#define OAI(buf)     (32768u + (unsigned)(buf) * 4096u) // A fp16 img (reused: sr)
#define ODW          40960u                            // float2[256]
#define OSIDX        43008u                            // int[64] row indices
#define OSE          43264u                            // float[64] e values
#define SMEM_BYTES   43520u

static __device__ __forceinline__ unsigned s2u(const void* p) {
    unsigned a;
    asm("{ .reg .u64 t; cvta.to.shared.u64 t, %1; cvt.u32.u64 %0, t; }" : "=r"(a) : "l"(p));
    return a;
}
static __device__ __forceinline__ void cp16(unsigned dst, const void* src) {
    asm volatile("cp.async.cg.shared.global [%0], [%1], 16;" :: "r"(dst), "l"(src));
}
#define CP_COMMIT() asm volatile("cp.async.commit_group;" ::: "memory")
#define CP_WAIT0()  asm volatile("cp.async.wait_group 0;" ::: "memory")

#define LDM4(r, addr) \
    asm volatile("ldmatrix.sync.aligned.m8n8.x4.shared.b16 {%0,%1,%2,%3}, [%4];" \
        : "=r"((r)[0]), "=r"((r)[1]), "=r"((r)[2]), "=r"((r)[3]) : "r"(addr))

#define MMAH(d, a, b0, b1) \
    asm volatile("mma.sync.aligned.m16n8k16.row.col.f32.f16.f16.f32 " \
        "{%0,%1,%2,%3}, {%4,%5,%6,%7}, {%8,%9}, {%0,%1,%2,%3};" \
        : "+f"((d)[0]), "+f"((d)[1]), "+f"((d)[2]), "+f"((d)[3]) \
        : "r"((a)[0]), "r"((a)[1]), "r"((a)[2]), "r"((a)[3]), "r"(b0), "r"(b1))

static __device__ __forceinline__ float tanha(float x) {
    float y;
    asm("tanh.approx.f32 %0, %1;" : "=f"(y) : "f"(x));
    return y;
}

// ---------------------------------------------------------------------------
// k_pre: 3 roles. blocks 0-63: compact+zero attn; 64-127: We prep;
//        128-191: decproj (4-way ILP)
// ---------------------------------------------------------------------------
__global__ __launch_bounds__(1024)
void k_pre(const int* __restrict__ mask, float* __restrict__ attn,
           const float* __restrict__ We,
           const float* __restrict__ dh, const float* __restrict__ Wd,
           const float* __restrict__ bd, const float* __restrict__ be,
           const float* __restrict__ Wa) {
    const int bid = blockIdx.x, t = threadIdx.x;
    if (bid < 64) {                                   // ---- compact ----
        const int b = bid;
        const int4 m = ((const int4*)(mask + b * S_))[t];
        int c0 = m.x != 0, c1 = m.y != 0, c2 = m.z != 0, c3 = m.w != 0;
        const int ls = c0 + c1 + c2 + c3;
        const int lane = t & 31, wid = t >> 5;
        int ws = ls;
#pragma unroll
        for (int o = 1; o < 32; o <<= 1) {
            int v = __shfl_up_sync(~0u, ws, o);
            if (lane >= o) ws += v;
        }
        __shared__ int wsum[32];
        if (lane == 31) wsum[wid] = ws;
        __syncthreads();
        if (t < 32) {
            int v = wsum[t];
#pragma unroll
            for (int o = 1; o < 32; o <<= 1) {
                int u = __shfl_up_sync(~0u, v, o);
                if (t >= o) v += u;
            }
            wsum[t] = v;
        }
        __syncthreads();
        int p = (wid ? wsum[wid - 1] : 0) + (ws - ls);
        const int s = t * 4;
        int* gi = g_idx + b * S_;
        float* at = attn + b * S_;
        if (c0) gi[p++] = s;     else at[s]     = 0.f;
        if (c1) gi[p++] = s + 1; else at[s + 1] = 0.f;
        if (c2) gi[p++] = s + 2; else at[s + 2] = 0.f;
        if (c3) gi[p++] = s + 3; else at[s + 3] = 0.f;
        if (t == 1023) g_cnt[b] = p;
    } else if (bid < 128) {                           // ---- We prep ----
        const int k = (bid - 64) * 4 + (t >> 8), n = t & 255;
        float v = We[k * 256 + n];
        int ch = k >> 5, kc = k & 31;
        int g = n >> 4, ks = kc >> 4, h16 = (kc >> 3) & 1;
        unsigned addr = (unsigned)((g * 2 + ks) * 512 + h16 * 256 + (n & 15) * 16 +
                                   (kc & 7) * 2);
        *(__half*)&g_Bt[ch][addr] = __float2half_rn(v);
    } else {                                          // ---- decproj ----
        const int b = bid - 128;
        __shared__ float sdh[DEC_];
        __shared__ float part[4][256];
        if (t < DEC_) sdh[t] = dh[b * DEC_ + t];
        __syncthreads();
        const int f = t & 255, q = t >> 8;            // 4 slices of 128 d
        const float* wp = Wd + (q * 128) * 256 + f;
        const float* hp = sdh + q * 128;
        float a0 = 0.f, a1 = 0.f, a2 = 0.f, a3 = 0.f;
#pragma unroll 8
        for (int d = 0; d < 128; d += 4) {            // 4 independent chains
            a0 += hp[d]     * wp[(d)     * 256];
            a1 += hp[d + 1] * wp[(d + 1) * 256];
            a2 += hp[d + 2] * wp[(d + 2) * 256];
            a3 += hp[d + 3] * wp[(d + 3) * 256];
        }
        part[q][f] = (a0 + a1) + (a2 + a3);
        __syncthreads();
        if (t < 256) {
            float v = part[0][t] + part[1][t] + part[2][t] + part[3][t] + bd[t] + be[t];
            g_dw[b * 256 + t] = make_float2(v, Wa[t]);
        }
    }
}

// ---------------------------------------------------------------------------
// k_scores: 64-row compacted tile, fp16 HMMA + fused tanh/exp/context epilogue
// ---------------------------------------------------------------------------
static __device__ __forceinline__ void loadB(unsigned sb, int c, int tid) {
#pragma unroll
    for (int i = 0; i < 4; ++i) {
        int slot = tid + i * 256;
        cp16(sb + OBI(c & 1) + (unsigned)slot * 16u, &g_Bt[c][slot * 16]);
    }
    CP_COMMIT();
}
static __device__ __forceinline__ void cvtstore(unsigned dst, float4 v0, float4 v1) {
    float vf[8] = {v0.x, v0.y, v0.z, v0.w, v1.x, v1.y, v1.z, v1.w};
    unsigned hu[4];
#pragma unroll
    for (int q = 0; q < 4; ++q) {
        __half2 hp = __halves2half2(__float2half_rn(vf[2 * q]),
                                    __float2half_rn(vf[2 * q + 1]));
        hu[q] = *(unsigned*)&hp;
    }
    asm volatile("st.shared.v4.b32 [%0], {%1,%2,%3,%4};"
                 :: "r"(dst), "r"(hu[0]), "r"(hu[1]), "r"(hu[2]), "r"(hu[3]));
}

__global__ __launch_bounds__(256, 2)
void k_scores(const float* __restrict__ enc) {
    const int b = blockIdx.x >> 6, tt = blockIdx.x & 63;
    const int cnt = g_cnt[b];
    const int tid = threadIdx.x;
    if (tt * MT >= cnt) return;                       // inactive: nothing to do

    extern __shared__ __align__(16) unsigned char sm[];
    const unsigned sb = s2u(sm);
    const int lane = tid & 31, w = tid >> 5;
    const int wr = w & 1, wc = w >> 1;

    const int r_ = tid >> 2, s_ = tid & 3;
    const int j = tt * MT + r_;
    const int row = g_idx[b * S_ + min(j, cnt - 1)];
    const float4* ap = (const float4*)(enc + ((size_t)b * S_ + row) * 256 + s_ * 8);
    const unsigned adst = (unsigned)(((r_ >> 4) * 2 + (s_ >> 1)) * 512 +
                                     (s_ & 1) * 256 + (r_ & 15) * 16);
    if ((tid & 3) == 0) ((int*)(sm + OSIDX))[r_] = row;

    loadB(sb, 0, tid);
    ((float2*)(sm + ODW))[tid] = g_dw[b * 256 + tid];

    float4 r0 = ap[0], r1 = ap[1];
    cvtstore(sb + OAI(0) + adst, r0, r1);
    CP_WAIT0();

    float acc[2][8][4];
#pragma unroll
    for (int mi = 0; mi < 2; ++mi)
#pragma unroll
        for (int ni = 0; ni < 8; ++ni)
#pragma unroll
            for (int q = 0; q < 4; ++q) acc[mi][ni][q] = 0.f;

    const unsigned a_lo = (unsigned)((lane & 15) * 16 + (lane >> 4) * 256);
    const unsigned b_lo = (unsigned)((lane & 7) * 16 + ((lane >> 4) & 1) * 128 +
                                     ((lane >> 3) & 1) * 256);

#pragma unroll 1
    for (int c = 0; c < 8; ++c) {
        const int buf = c & 1;
        __syncthreads();
        if (c < 7) {
            loadB(sb, c + 1, tid);
            r0 = ap[(c + 1) * 8];
            r1 = ap[(c + 1) * 8 + 1];
        }
        const unsigned ah_b = sb + OAI(buf) + a_lo;
        const unsigned bh_b = sb + OBI(buf) + b_lo;
#pragma unroll
        for (int ks = 0; ks < 2; ++ks) {
            unsigned af[2][4], bh[8][2];
#pragma unroll
            for (int mi = 0; mi < 2; ++mi)
                LDM4(af[mi], ah_b + (unsigned)(((wr * 2 + mi) * 2 + ks) * 512));
#pragma unroll
            for (int p = 0; p < 4; ++p) {
                const unsigned blk = (unsigned)(((wc * 4 + p) * 2 + ks) * 512);
                unsigned r4[4];
                LDM4(r4, bh_b + blk);
                bh[2 * p][0] = r4[0]; bh[2 * p][1] = r4[1];
                bh[2 * p + 1][0] = r4[2]; bh[2 * p + 1][1] = r4[3];
            }
#pragma unroll
            for (int mi = 0; mi < 2; ++mi)
#pragma unroll
                for (int ni = 0; ni < 8; ++ni)
                    MMAH(acc[mi][ni], af[mi], bh[ni][0], bh[ni][1]);
        }
        if (c < 7) {
            cvtstore(sb + OAI(buf ^ 1) + adst, r0, r1);
            CP_WAIT0();
        }
    }

    // ---- Epilogue 1: score partials = sum_cols Wa * tanh(dpe + v) ----
    const float2* sdw = (const float2*)(sm + ODW);
    float* red = (float*)(sm + OBI(0));
#pragma unroll
    for (int mi = 0; mi < 2; ++mi) {
        float p0 = 0.f, p1 = 0.f;
#pragma unroll
        for (int ni = 0; ni < 8; ++ni) {
            int cc = wc * 64 + ni * 8 + 2 * (lane & 3);
            float2 w0 = sdw[cc], w1 = sdw[cc + 1];
            p0 += w0.y * tanha(acc[mi][ni][0] + w0.x) +
                  w1.y * tanha(acc[mi][ni][1] + w1.x);
            p1 += w0.y * tanha(acc[mi][ni][2] + w0.x) +
                  w1.y * tanha(acc[mi][ni][3] + w1.x);
        }
        p0 += __shfl_xor_sync(~0u, p0, 1); p0 += __shfl_xor_sync(~0u, p0, 2);
        p1 += __shfl_xor_sync(~0u, p1, 1); p1 += __shfl_xor_sync(~0u, p1, 2);
        if ((lane & 3) == 0) {
            int r = wr * 32 + mi * 16 + (lane >> 2);
            red[r * 5 + wc] = p0;
            red[(r + 8) * 5 + wc] = p1;
        }
    }
    __syncthreads();
    // ---- Epilogue 2: e = exp(score) (safe: |score| <= ~13), store ----
    float* se = (float*)(sm + OSE);
    if (tid < MT) {
        float s = red[tid * 5] + red[tid * 5 + 1] + red[tid * 5 + 2] + red[tid * 5 + 3];
        float e = (tt * MT + tid < cnt) ? __expf(s) : 0.f;
        se[tid] = e;
        g_scores[b * S_ + tt * MT + tid] = e;
    }
    __syncthreads();
    if (tid < 32) {                                   // tile sum of e
        float v = se[tid] + se[tid + 32];
#pragma unroll
        for (int o = 16; o; o >>= 1) v += __shfl_xor_sync(~0u, v, o);
        if (tid == 0) g_esum[b * 64 + tt] = v;
    }
    // ---- Epilogue 3: ctx partial = sum_r e[r] * enc[row_r, :] (L2 hits) ----
    {
        const int c4 = tid & 63, rg = tid >> 6;
        const int* sidx = (const int*)(sm + OSIDX);
        const float4* e4 = (const float4*)enc + (size_t)b * S_ * 64;
        float4 a4 = make_float4(0.f, 0.f, 0.f, 0.f);
#pragma unroll 4
        for (int i = 0; i < 16; ++i) {
            int r = rg * 16 + i;
            float wv = se[r];
            float4 ev = e4[(size_t)sidx[r] * 64 + c4];
            a4.x += wv * ev.x; a4.y += wv * ev.y; a4.z += wv * ev.z; a4.w += wv * ev.w;
        }
        float4* sr = (float4*)(sm + OAI(0));
        sr[rg * 64 + c4] = a4;
        __syncthreads();
        if (tid < 64) {
            float4 q0 = sr[tid], q1 = sr[64 + tid], q2 = sr[128 + tid], q3 = sr[192 + tid];
            float4 o;
            o.x = q0.x + q1.x + q2.x + q3.x;
            o.y = q0.y + q1.y + q2.y + q3.y;
            o.z = q0.z + q1.z + q2.z + q3.z;
            o.w = q0.w + q1.w + q2.w + q3.w;
            ((float4*)g_cpart)[((size_t)b * 64 + tt) * 64 + tid] = o;
        }
    }
}

// ---------------------------------------------------------------------------
// k_finish: per batch: sum active tiles -> ctx = acc/sum; attn scatter = e/sum
// ---------------------------------------------------------------------------
__global__ __launch_bounds__(1024)
void k_finish(float* __restrict__ ctx, float* __restrict__ attn) {
    const int b = blockIdx.x, t = threadIdx.x;
    const int cnt = g_cnt[b];
    const int ntiles = (cnt + MT - 1) / MT;           // only active tiles
    __shared__ float s_e[64];
    __shared__ float s_inv;
    if (t < 64) s_e[t] = (t < ntiles) ? g_esum[b * 64 + t] : 0.f;
    __syncthreads();
    if (t < 32) {
        float v = s_e[t] + s_e[t + 32];
#pragma unroll
        for (int o = 16; o; o >>= 1) v += __shfl_xor_sync(~0u, v, o);
        if (t == 0) s_inv = 1.f / v;
    }
    __syncthreads();
    const float inv = s_inv;
    if (t < 256) {
        const float* cp = g_cpart + (size_t)b * 64 * 256 + t;
        float a0 = 0.f, a1 = 0.f, a2 = 0.f, a3 = 0.f;
        int t2 = 0;
        for (; t2 + 4 <= ntiles; t2 += 4) {           // 4 independent chains
            a0 += cp[(t2)     * 256];
            a1 += cp[(t2 + 1) * 256];
            a2 += cp[(t2 + 2) * 256];
            a3 += cp[(t2 + 3) * 256];
        }
        for (; t2 < ntiles; ++t2) a0 += cp[t2 * 256];
        ctx[b * 256 + t] = ((a0 + a1) + (a2 + a3)) * inv;
    }
    for (int j = t; j < cnt; j += 1024)
        attn[b * S_ + g_idx[b * S_ + j]] = g_scores[b * S_ + j] * inv;
}

// ---------------------------------------------------------------------------
extern "C" void kernel_launch(void* const* d_in, const int* in_sizes, int n_in,
                              void* d_out, int out_size) {
    const float* dh   = (const float*)d_in[0];
    const float* enc  = (const float*)d_in[1];
    const int*   mask = (const int*)  d_in[2];
    const float* Wd   = (const float*)d_in[3];
    const float* bd   = (const float*)d_in[4];
    const float* We   = (const float*)d_in[5];
    const float* be   = (const float*)d_in[6];
    const float* Wa   = (const float*)d_in[7];
    // d_in[8] = ba: uniform shift on scores, cancels in softmax

    float* out  = (float*)d_out;
    float* ctx  = out;
    float* attn = out + B_ * ENC_;

    cudaFuncSetAttribute(k_scores, cudaFuncAttributeMaxDynamicSharedMemorySize, SMEM_BYTES);

    k_pre<<<192, 1024>>>(mask, attn, We, dh, Wd, bd, be, Wa);
    k_scores<<<B_ * 64, 256, SMEM_BYTES>>>(enc);
    k_finish<<<B_, 1024>>>(ctx, attn);
}